// round 3
// baseline (speedup 1.0000x reference)
#include <cuda_runtime.h>

// KroneckerAddress: B=64 rows, U=3 parts of DP=128, K=32.
// Top-32 of softmax(z0) (x) softmax(z1) (x) softmax(z2), per row.
// Output: [indices(64*32) as float | weights(64*32)].
//
// Rank pruning: triple (i,j,k) (1-indexed ranks) needs i*j*k <= 32 -> 300 candidates.
// Value pruning: L = max over axes of (top0*top0*rank31) is a certified lower bound
// on the 32nd-largest candidate (fp32 multiply is monotone), so candidates < L are
// dropped before the O(n^2) ranking. Typically ~40-80 survive.

#define BB 64
#define DP 128
#define KK 32
#define NC 300
#define NPAIR 119

typedef unsigned long long u64;
typedef unsigned int u32;

// (i<<8)|j for all pairs with (i+1)*(j+1) <= 32, i-major order (119 entries)
__constant__ unsigned short PAIRIJ[NPAIR] = {
    // i=0, j=0..31
    0x0000,0x0001,0x0002,0x0003,0x0004,0x0005,0x0006,0x0007,
    0x0008,0x0009,0x000A,0x000B,0x000C,0x000D,0x000E,0x000F,
    0x0010,0x0011,0x0012,0x0013,0x0014,0x0015,0x0016,0x0017,
    0x0018,0x0019,0x001A,0x001B,0x001C,0x001D,0x001E,0x001F,
    // i=1, j=0..15
    0x0100,0x0101,0x0102,0x0103,0x0104,0x0105,0x0106,0x0107,
    0x0108,0x0109,0x010A,0x010B,0x010C,0x010D,0x010E,0x010F,
    // i=2, j=0..9
    0x0200,0x0201,0x0202,0x0203,0x0204,0x0205,0x0206,0x0207,0x0208,0x0209,
    // i=3, j=0..7
    0x0300,0x0301,0x0302,0x0303,0x0304,0x0305,0x0306,0x0307,
    // i=4, j=0..5
    0x0400,0x0401,0x0402,0x0403,0x0404,0x0405,
    // i=5, j=0..4
    0x0500,0x0501,0x0502,0x0503,0x0504,
    // i=6, j=0..3
    0x0600,0x0601,0x0602,0x0603,
    // i=7, j=0..3
    0x0700,0x0701,0x0702,0x0703,
    // i=8, j=0..2
    0x0800,0x0801,0x0802,
    // i=9, j=0..2
    0x0900,0x0901,0x0902,
    // i=10..15, j=0..1
    0x0A00,0x0A01,0x0B00,0x0B01,0x0C00,0x0C01,
    0x0D00,0x0D01,0x0E00,0x0E01,0x0F00,0x0F01,
    // i=16..31, j=0
    0x1000,0x1100,0x1200,0x1300,0x1400,0x1500,0x1600,0x1700,
    0x1800,0x1900,0x1A00,0x1B00,0x1C00,0x1D00,0x1E00,0x1F00};

// T32[n] = floor(32/n)
__constant__ int T32[33] = {
    0,32,16,10,8,6,5,4,4,3,3,2,2,2,2,2,2,
    1,1,1,1,1,1,1,1,1,1,1,1,1,1,1,1};

__global__ __launch_bounds__(384, 3)
void kron_topk_kernel(const float* __restrict__ z,
                      const float* __restrict__ log_tau,
                      float* __restrict__ out,
                      int wofs)
{
    const int b    = blockIdx.x;
    const int t    = threadIdx.x;       // 0..383
    const int g    = t >> 7;            // part 0..2
    const int lt   = t & 127;           // index within part
    const int w    = t >> 5;            // warp 0..11
    const int lane = t & 31;

    __shared__ __align__(16) u64 keys[3][DP];   // per-part packed (e_bits<<32)|~idx
    __shared__ float tvv[3][KK];                // per-part top-32 values, desc
    __shared__ int   tii[3][KK];                // per-part top-32 original indices
    __shared__ float redB[12];
    __shared__ float Ssh[3];                    // per-part exp sums
    __shared__ __align__(16) u64 kv[NC];        // surviving candidate keys
    __shared__ int ccount;

    // ---- unnormalized exp (no max-subtract: |z/tau| small; sum folded into output) ----
    const float inv_tau = __expf(-log_tau[0]);
    const float e = __expf(z[(size_t)b * (3 * DP) + t] * inv_tau);

    const u64 myk = ((u64)__float_as_uint(e) << 32) | (u64)(u32)(~lt);
    keys[g][lt] = myk;

    float s = e;
    #pragma unroll
    for (int o = 16; o > 0; o >>= 1)
        s += __shfl_xor_sync(0xFFFFFFFFu, s, o);
    if (lane == 0) redB[w] = s;
    if (t == 0) ccount = 0;
    __syncthreads();

    if (lt == 0)
        Ssh[g] = (redB[g*4+0] + redB[g*4+1]) + (redB[g*4+2] + redB[g*4+3]);

    // ---- per-part top-32 via rank counting on packed keys (vectorized LDS.128) ----
    {
        const ulonglong2* kp = (const ulonglong2*)keys[g];
        int r = 0;
        #pragma unroll 8
        for (int q = 0; q < DP / 2; q++) {
            ulonglong2 kk = kp[q];
            r += (int)(kk.x > myk) + (int)(kk.y > myk);
        }
        if (r < KK) { tvv[g][r] = e; tii[g][r] = lt; }
    }
    __syncthreads();

    // ---- certified threshold: 32nd-largest >= each axis-chain minimum ----
    const float L = fmaxf(fmaxf((tvv[0][0] * tvv[1][0]) * tvv[2][KK-1],
                                (tvv[0][0] * tvv[1][KK-1]) * tvv[2][0]),
                                (tvv[0][KK-1] * tvv[1][0]) * tvv[2][0]);

    // ---- enumerate candidates, keep only v >= L (descending in k -> early stop) ----
    if (t < NPAIR) {
        const int ij = PAIRIJ[t];
        const int i = ij >> 8, j = ij & 0xFF;
        const float vij = tvv[0][i] * tvv[1][j];
        const int   gij = tii[0][i] * (DP * DP) + tii[1][j] * DP;
        const int limk = T32[(i + 1) * (j + 1)];
        int cnt = 0;
        while (cnt < limk && vij * tvv[2][cnt] >= L) cnt++;
        if (cnt > 0) {
            const int pos = atomicAdd(&ccount, cnt);
            for (int k = 0; k < cnt; k++) {
                const float v = vij * tvv[2][k];
                const u32 gidx = (u32)(gij + tii[2][k]);
                kv[pos + k] = ((u64)__float_as_uint(v) << 32) | (u64)(u32)(~gidx);
            }
        }
    }
    __syncthreads();

    // ---- global rank among survivors (>=32 guaranteed); emit top-32 ----
    const int nc = ccount;
    if (t < nc) {
        const u64 mk = kv[t];
        int r = 0;
        #pragma unroll 4
        for (int d = 0; d < nc; d++)
            r += (int)(kv[d] > mk);
        if (r < KK) {
            const u32 gidx = ~(u32)mk;
            const float v = __uint_as_float((u32)(mk >> 32));
            const float invS = 1.0f / ((Ssh[0] * Ssh[1]) * Ssh[2]);
            out[b * KK + r]        = (float)gidx;
            out[wofs + b * KK + r] = v * invS;
        }
    }
}

extern "C" void kernel_launch(void* const* d_in, const int* in_sizes, int n_in,
                              void* d_out, int out_size)
{
    const float* z       = (const float*)d_in[0];
    const float* log_tau = (const float*)d_in[1];
    float* out = (float*)d_out;
    kron_topk_kernel<<<BB, 384>>>(z, log_tau, out, out_size / 2);
}

// round 4
// speedup vs baseline: 1.1895x; 1.1895x over previous
#include <cuda_runtime.h>

// KroneckerAddress: B=64 rows, U=3 parts of DP=128, K=32.
// Top-32 of softmax(z0) (x) softmax(z1) (x) softmax(z2), per row.
// Output: [indices(64*32) as float | weights(64*32)].
//
// Rank pruning: rank triple (i,j,k) (1-indexed) needs i*j*k <= 32 -> exactly 300
// candidates, enumerated via a constant table (one thread per candidate, no serial
// loops). Value pruning: L = max over the 3 axes of (top0*top0*rank31) certifies
// >=32 candidates >= L (fp32 mult is monotone), so v < L is dropped pre-ranking.

#define BB 64
#define DP 128
#define KK 32
#define NC 300

typedef unsigned long long u64;
typedef unsigned int u32;

// All 300 rank triples (i<<10)|(j<<5)|k with (i+1)(j+1)(k+1) <= 32, i-major.
__constant__ unsigned short CAND[NC] = {
    // i=0,j=0,k=0..31
    0,1,2,3,4,5,6,7,8,9,10,11,12,13,14,15,
    16,17,18,19,20,21,22,23,24,25,26,27,28,29,30,31,
    // i=0,j=1,k=0..15
    32,33,34,35,36,37,38,39,40,41,42,43,44,45,46,47,
    // i=0,j=2..3
    64,65,66,67,68,69,70,71,72,73,  96,97,98,99,100,101,102,103,
    // i=0,j=4..7
    128,129,130,131,132,133, 160,161,162,163,164,
    192,193,194,195, 224,225,226,227,
    // i=0,j=8..15
    256,257,258, 288,289,290, 320,321, 352,353, 384,385, 416,417, 448,449, 480,481,
    // i=0,j=16..31 (k=0)
    512,544,576,608,640,672,704,736,768,800,832,864,896,928,960,992,
    // i=1,j=0,k=0..15
    1024,1025,1026,1027,1028,1029,1030,1031,1032,1033,1034,1035,1036,1037,1038,1039,
    // i=1,j=1..7
    1056,1057,1058,1059,1060,1061,1062,1063,
    1088,1089,1090,1091,1092, 1120,1121,1122,1123,
    1152,1153,1154, 1184,1185, 1216,1217, 1248,1249,
    // i=1,j=8..15 (k=0)
    1280,1312,1344,1376,1408,1440,1472,1504,
    // i=2
    2048,2049,2050,2051,2052,2053,2054,2055,2056,2057,
    2080,2081,2082,2083,2084, 2112,2113,2114, 2144,2145, 2176,2177,
    2208,2240,2272,2304,2336,
    // i=3
    3072,3073,3074,3075,3076,3077,3078,3079,
    3104,3105,3106,3107, 3136,3137, 3168,3169, 3200,3232,3264,3296,
    // i=4
    4096,4097,4098,4099,4100,4101, 4128,4129,4130, 4160,4161, 4192,4224,4256,
    // i=5
    5120,5121,5122,5123,5124, 5152,5153, 5184,5216,5248,
    // i=6
    6144,6145,6146,6147, 6176,6177, 6208,6240,
    // i=7
    7168,7169,7170,7171, 7200,7201, 7232,7264,
    // i=8
    8192,8193,8194, 8224, 8256,
    // i=9
    9216,9217,9218, 9248, 9280,
    // i=10..15
    10240,10241,10272, 11264,11265,11296, 12288,12289,12320,
    13312,13313,13344, 14336,14337,14368, 15360,15361,15392,
    // i=16..31 (j=0,k=0)
    16384,17408,18432,19456,20480,21504,22528,23552,
    24576,25600,26624,27648,28672,29696,30720,31744};

__global__ __launch_bounds__(384, 3)
void kron_topk_kernel(const float* __restrict__ z,
                      const float* __restrict__ log_tau,
                      float* __restrict__ out,
                      int wofs)
{
    const int b    = blockIdx.x;
    const int t    = threadIdx.x;       // 0..383
    const int g    = t >> 7;            // part 0..2
    const int lt   = t & 127;           // index within part
    const int w    = t >> 5;            // warp 0..11
    const int lane = t & 31;

    __shared__ __align__(16) u64 keys[3][DP];   // per-part packed (e_bits<<32)|~idx
    __shared__ float tvv[3][KK];                // per-part top-32 values, desc
    __shared__ int   tii[3][KK];                // per-part top-32 original indices
    __shared__ float redB[12];
    __shared__ float Ssh[3];                    // per-part exp sums
    __shared__ __align__(16) u64 kv[NC];        // surviving candidate keys
    __shared__ int ccount;

    // ---- unnormalized exp (no max-subtract; normalization folded into output) ----
    const float inv_tau = __expf(-log_tau[0]);
    const float e = __expf(z[(size_t)b * (3 * DP) + t] * inv_tau);

    const u64 myk = ((u64)__float_as_uint(e) << 32) | (u64)(u32)(~lt);
    keys[g][lt] = myk;

    float s = e;
    #pragma unroll
    for (int o = 16; o > 0; o >>= 1)
        s += __shfl_xor_sync(0xFFFFFFFFu, s, o);
    if (lane == 0) redB[w] = s;
    if (t == 0) ccount = 0;
    __syncthreads();

    if (lt == 0)
        Ssh[g] = (redB[g*4+0] + redB[g*4+1]) + (redB[g*4+2] + redB[g*4+3]);

    // ---- per-part top-32 via rank counting on packed keys (LDS.128, broadcast) ----
    {
        const ulonglong2* kp = (const ulonglong2*)keys[g];
        int r = 0;
        #pragma unroll 8
        for (int q = 0; q < DP / 2; q++) {
            ulonglong2 kk = kp[q];
            r += (int)(kk.x > myk) + (int)(kk.y > myk);
        }
        if (r < KK) { tvv[g][r] = e; tii[g][r] = lt; }
    }
    __syncthreads();

    // ---- certified lower bound on the 32nd-largest candidate ----
    const float L = fmaxf(fmaxf((tvv[0][0] * tvv[1][0]) * tvv[2][KK-1],
                                (tvv[0][0] * tvv[1][KK-1]) * tvv[2][0]),
                                (tvv[0][KK-1] * tvv[1][0]) * tvv[2][0]);

    // ---- flat candidate evaluation: one thread per triple, no serial chains ----
    {
        bool keep = false;
        u64 key = 0;
        if (t < NC) {
            const u32 c = CAND[t];
            const int i = c >> 10, j = (c >> 5) & 31, k = c & 31;
            const float v = (tvv[0][i] * tvv[1][j]) * tvv[2][k];
            if (v >= L) {
                keep = true;
                const u32 gidx = (u32)(tii[0][i] * (DP * DP) + tii[1][j] * DP + tii[2][k]);
                key = ((u64)__float_as_uint(v) << 32) | (u64)(u32)(~gidx);
            }
        }
        // warp-aggregated compaction into kv[]
        const u32 mask = __ballot_sync(0xFFFFFFFFu, keep);
        const int nkeep = __popc(mask);
        int base = 0;
        if (lane == 0 && nkeep) base = atomicAdd(&ccount, nkeep);
        base = __shfl_sync(0xFFFFFFFFu, base, 0);
        if (keep)
            kv[base + __popc(mask & ((1u << lane) - 1u))] = key;
    }
    __syncthreads();

    // ---- global rank among survivors (>=32 guaranteed); emit top-32 ----
    const int nc = ccount;
    if (t < nc) {
        const u64 mk = kv[t];
        int r = 0;
        #pragma unroll 4
        for (int d = 0; d < nc; d++)
            r += (int)(kv[d] > mk);
        if (r < KK) {
            const u32 gidx = ~(u32)mk;
            const float v = __uint_as_float((u32)(mk >> 32));
            const float invS = 1.0f / ((Ssh[0] * Ssh[1]) * Ssh[2]);
            out[b * KK + r]        = (float)gidx;
            out[wofs + b * KK + r] = v * invS;
        }
    }
}

extern "C" void kernel_launch(void* const* d_in, const int* in_sizes, int n_in,
                              void* d_out, int out_size)
{
    const float* z       = (const float*)d_in[0];
    const float* log_tau = (const float*)d_in[1];
    float* out = (float*)d_out;
    kron_topk_kernel<<<BB, 384>>>(z, log_tau, out, out_size / 2);
}

// round 5
// speedup vs baseline: 1.5000x; 1.2610x over previous
#include <cuda_runtime.h>

// KroneckerAddress: B=64 rows, U=3 parts of DP=128, K=32.
// Top-32 of softmax(z0) (x) softmax(z1) (x) softmax(z2), per row.
// Output: [indices(64*32) as float | weights(64*32)].
//
// Rank pruning: rank triple (i,j,k) (1-indexed) needs i*j*k <= 32 -> 300 candidates
// (constant table, one thread each). Value pruning: L = max over 3 axes of
// (top0*top0*rank31) certifies >=32 candidates >= L, so v < L is dropped pre-rank.
// Per-part scan uses u32 keys: (e_bits & ~0x7F) | (127-idx) -> single u32 compare,
// distinct keys, stable tiebreak; value perturbation <= 2^-17 relative.

#define BB 64
#define DP 128
#define KK 32
#define NC 300
#define NCP 308   // NC padded to multiple of 8 (zero-filled)

typedef unsigned long long u64;
typedef unsigned int u32;

// All 300 rank triples (i<<10)|(j<<5)|k with (i+1)(j+1)(k+1) <= 32, i-major.
__constant__ unsigned short CAND[NC] = {
    0,1,2,3,4,5,6,7,8,9,10,11,12,13,14,15,
    16,17,18,19,20,21,22,23,24,25,26,27,28,29,30,31,
    32,33,34,35,36,37,38,39,40,41,42,43,44,45,46,47,
    64,65,66,67,68,69,70,71,72,73,  96,97,98,99,100,101,102,103,
    128,129,130,131,132,133, 160,161,162,163,164,
    192,193,194,195, 224,225,226,227,
    256,257,258, 288,289,290, 320,321, 352,353, 384,385, 416,417, 448,449, 480,481,
    512,544,576,608,640,672,704,736,768,800,832,864,896,928,960,992,
    1024,1025,1026,1027,1028,1029,1030,1031,1032,1033,1034,1035,1036,1037,1038,1039,
    1056,1057,1058,1059,1060,1061,1062,1063,
    1088,1089,1090,1091,1092, 1120,1121,1122,1123,
    1152,1153,1154, 1184,1185, 1216,1217, 1248,1249,
    1280,1312,1344,1376,1408,1440,1472,1504,
    2048,2049,2050,2051,2052,2053,2054,2055,2056,2057,
    2080,2081,2082,2083,2084, 2112,2113,2114, 2144,2145, 2176,2177,
    2208,2240,2272,2304,2336,
    3072,3073,3074,3075,3076,3077,3078,3079,
    3104,3105,3106,3107, 3136,3137, 3168,3169, 3200,3232,3264,3296,
    4096,4097,4098,4099,4100,4101, 4128,4129,4130, 4160,4161, 4192,4224,4256,
    5120,5121,5122,5123,5124, 5152,5153, 5184,5216,5248,
    6144,6145,6146,6147, 6176,6177, 6208,6240,
    7168,7169,7170,7171, 7200,7201, 7232,7264,
    8192,8193,8194, 8224, 8256,
    9216,9217,9218, 9248, 9280,
    10240,10241,10272, 11264,11265,11296, 12288,12289,12320,
    13312,13313,13344, 14336,14337,14368, 15360,15361,15392,
    16384,17408,18432,19456,20480,21504,22528,23552,
    24576,25600,26624,27648,28672,29696,30720,31744};

__global__ __launch_bounds__(384, 3)
void kron_topk_kernel(const float* __restrict__ z,
                      const float* __restrict__ log_tau,
                      float* __restrict__ out,
                      int wofs)
{
    const int b    = blockIdx.x;
    const int t    = threadIdx.x;       // 0..383
    const int g    = t >> 7;            // part 0..2
    const int lt   = t & 127;           // index within part
    const int w    = t >> 5;            // warp 0..11
    const int lane = t & 31;

    __shared__ __align__(16) u32 keys[3][DP];   // masked-float keys, distinct
    __shared__ float tvv[3][KK];                // per-part top-32 values, desc
    __shared__ int   tii[3][KK];                // per-part top-32 indices
    __shared__ float Ssh[3];                    // per-part exp sums
    __shared__ __align__(16) u64 kv[NCP];       // surviving candidates (zero-padded)
    __shared__ int ccount;

    // zero-pad kv + init (overlaps the global loads below)
    if (t < NCP) kv[t] = 0ULL;
    if (t == 0) ccount = 0;

    // ---- unnormalized exp (normalization folded into output) ----
    const float inv_tau = __expf(-log_tau[0]);
    const float e = __expf(z[(size_t)b * (3 * DP) + t] * inv_tau);

    // distinct monotone key: value high bits | stable index tiebreak
    const u32 key = (__float_as_uint(e) & 0xFFFFFF80u) | (u32)(127 - lt);
    keys[g][lt] = key;
    __syncthreads();

    // ---- per-part top-32 via rank counting on u32 keys (LDS.128 = 4 keys) ----
    {
        const uint4* kp = (const uint4*)keys[g];
        int r = 0;
        #pragma unroll
        for (int q = 0; q < DP / 4; q++) {
            const uint4 kk = kp[q];
            r += (int)(kk.x > key) + (int)(kk.y > key)
               + (int)(kk.z > key) + (int)(kk.w > key);
        }
        if (r < KK) { tvv[g][r] = __uint_as_float(key); tii[g][r] = lt; }
    }
    __syncthreads();

    // ---- flat candidate evaluation: one thread per triple ----
    bool keep = false;
    u64 ckey = 0;
    if (t < NC) {
        // certified lower bound on the 32nd-largest candidate
        const float L = fmaxf(fmaxf((tvv[0][0] * tvv[1][0]) * tvv[2][KK-1],
                                    (tvv[0][0] * tvv[1][KK-1]) * tvv[2][0]),
                                    (tvv[0][KK-1] * tvv[1][0]) * tvv[2][0]);
        const u32 c = CAND[t];
        const int i = c >> 10, j = (c >> 5) & 31, k = c & 31;
        const float v = (tvv[0][i] * tvv[1][j]) * tvv[2][k];
        if (v >= L) {
            keep = true;
            const u32 gidx = (u32)(tii[0][i] * (DP * DP) + tii[1][j] * DP + tii[2][k]);
            ckey = ((u64)__float_as_uint(v) << 32) | (u64)(u32)(~gidx);
        }
    }
    if (w < 10) {
        // warp-aggregated compaction into kv[]
        const u32 mask = __ballot_sync(0xFFFFFFFFu, keep);
        const int nkeep = __popc(mask);
        int base = 0;
        if (lane == 0 && nkeep) base = atomicAdd(&ccount, nkeep);
        base = __shfl_sync(0xFFFFFFFFu, base, 0);
        if (keep)
            kv[base + __popc(mask & ((1u << lane) - 1u))] = ckey;
    } else if (w == 10) {
        // off-critical-path: part sums from keys (rel err < 2^-17 per term)
        float a0 = 0.f, a1 = 0.f, a2 = 0.f;
        #pragma unroll
        for (int m = 0; m < 4; m++) {
            a0 += __uint_as_float(keys[0][lane + 32 * m]);
            a1 += __uint_as_float(keys[1][lane + 32 * m]);
            a2 += __uint_as_float(keys[2][lane + 32 * m]);
        }
        #pragma unroll
        for (int o = 16; o > 0; o >>= 1) {
            a0 += __shfl_xor_sync(0xFFFFFFFFu, a0, o);
            a1 += __shfl_xor_sync(0xFFFFFFFFu, a1, o);
            a2 += __shfl_xor_sync(0xFFFFFFFFu, a2, o);
        }
        if (lane == 0) { Ssh[0] = a0; Ssh[1] = a1; Ssh[2] = a2; }
    }
    __syncthreads();

    // ---- global rank among survivors (>=32 guaranteed); emit top-32 ----
    const int nc = ccount;
    if (t < nc) {
        const u64 mk = kv[t];
        const int ncr2 = ((nc + 7) & ~7) >> 1;   // pairs, multiple of 4
        const ulonglong2* kp = (const ulonglong2*)kv;
        int r = 0;
        for (int q = 0; q < ncr2; q += 4) {
            #pragma unroll
            for (int m = 0; m < 4; m++) {
                const ulonglong2 kk = kp[q + m];
                r += (int)(kk.x > mk) + (int)(kk.y > mk);
            }
        }
        if (r < KK) {
            const u32 gidx = ~(u32)mk;
            const float v = __uint_as_float((u32)(mk >> 32));
            const float invS = 1.0f / ((Ssh[0] * Ssh[1]) * Ssh[2]);
            out[b * KK + r]        = (float)gidx;
            out[wofs + b * KK + r] = v * invS;
        }
    }
}

extern "C" void kernel_launch(void* const* d_in, const int* in_sizes, int n_in,
                              void* d_out, int out_size)
{
    const float* z       = (const float*)d_in[0];
    const float* log_tau = (const float*)d_in[1];
    float* out = (float*)d_out;
    kron_topk_kernel<<<BB, 384>>>(z, log_tau, out, out_size / 2);
}